// round 1
// baseline (speedup 1.0000x reference)
#include <cuda_runtime.h>

// Problem constants (fixed by the reference: xx is (N, M) fp32 row-major, diag is (N,))
#define NN 4096
#define MM 4096
#define ROW_SPLITS 64
#define ROWS_PER (NN / ROW_SPLITS)   // 64 rows per partial block

// Scratch (no allocations allowed) — fully overwritten each launch, so replay-safe.
__device__ float g_part[ROW_SPLITS * MM];  // partial exp-sums per (split, column)
__device__ float g_ssum[MM];               // Ssum[m] = sum_j exp(xx[j,m])
__device__ float g_em1[NN];                // em1[i] = expm1(diag[i])

// Kernel 1: partial column sums of exp(x). Grid (MM/4/128, ROW_SPLITS), block 128.
// Each thread owns 4 consecutive columns (float4) and walks 64 rows. Coalesced.
__global__ void __launch_bounds__(128) col_partial_exp_sum(const float* __restrict__ xx) {
    const int c4 = blockIdx.x * 128 + threadIdx.x;       // float4 column index
    const int r0 = blockIdx.y * ROWS_PER;
    const float4* __restrict__ x4 = (const float4*)xx;
    const int stride4 = MM / 4;

    float4 acc = make_float4(0.f, 0.f, 0.f, 0.f);
    long base = (long)r0 * stride4 + c4;
#pragma unroll 8
    for (int j = 0; j < ROWS_PER; ++j) {
        float4 v = x4[base + (long)j * stride4];
        acc.x += __expf(v.x);
        acc.y += __expf(v.y);
        acc.z += __expf(v.z);
        acc.w += __expf(v.w);
    }
    ((float4*)g_part)[blockIdx.y * stride4 + c4] = acc;
}

// Kernel 2: fold the 64 partials per column, and precompute expm1(diag).
// Grid 16, block 256 (4096 threads; N == M == 4096 so one thread does both jobs).
__global__ void __launch_bounds__(256) reduce_and_prep(const float* __restrict__ diag) {
    const int m = blockIdx.x * 256 + threadIdx.x;
    float s = 0.f;
#pragma unroll 8
    for (int k = 0; k < ROW_SPLITS; ++k) s += g_part[k * MM + m];
    g_ssum[m] = s;
    g_em1[m] = expm1f(diag[m]);
}

// Kernel 3: out[i,m] = log( Ssum[m] + em1[i] * exp(xx[i,m]) )
//   (== S + log1p(expm1(d_i) * exp(x - S)) exactly, with S = log(Ssum))
// Grid (MM/4/256, NN), block 256. Float4 streaming; em1[i] broadcasts within block.
__global__ void __launch_bounds__(256) fuse_out(const float* __restrict__ xx,
                                               float* __restrict__ out) {
    const int i = blockIdx.y;
    const int c4 = blockIdx.x * 256 + threadIdx.x;
    const int stride4 = MM / 4;
    const float em = g_em1[i];

    const float4* __restrict__ x4 = (const float4*)xx;
    const float4* __restrict__ s4 = (const float4*)g_ssum;

    float4 v = x4[(long)i * stride4 + c4];
    float4 s = s4[c4];

    float4 o;
    o.x = __logf(fmaf(em, __expf(v.x), s.x));
    o.y = __logf(fmaf(em, __expf(v.y), s.y));
    o.z = __logf(fmaf(em, __expf(v.z), s.z));
    o.w = __logf(fmaf(em, __expf(v.w), s.w));

    ((float4*)out)[(long)i * stride4 + c4] = o;
}

extern "C" void kernel_launch(void* const* d_in, const int* in_sizes, int n_in,
                              void* d_out, int out_size) {
    const float* xx   = (const float*)d_in[0];   // (4096, 4096) fp32 row-major
    const float* diag = (const float*)d_in[1];   // (4096,) fp32
    float* out        = (float*)d_out;           // (4096, 4096) fp32

    dim3 g1(MM / 4 / 128, ROW_SPLITS);  // (8, 64)
    col_partial_exp_sum<<<g1, 128>>>(xx);

    reduce_and_prep<<<MM / 256, 256>>>(diag);

    dim3 g3(MM / 4 / 256, NN);          // (4, 4096)
    fuse_out<<<g3, 256>>>(xx, out);
}

// round 2
// speedup vs baseline: 1.0549x; 1.0549x over previous
#include <cuda_runtime.h>

// Problem constants (fixed by the reference: xx is (N, M) fp32 row-major, diag is (N,))
#define NN 4096
#define MM 4096
#define ROW_SPLITS 128
#define ROWS_PER (NN / ROW_SPLITS)   // 32 rows per partial block

// Scratch (no allocations allowed) — fully overwritten each launch, replay-safe.
__device__ float g_part[ROW_SPLITS * MM];  // partial exp-sums per (split, column)
__device__ float g_ssum[MM];               // Ssum[m] = sum_j exp(xx[j,m])

// Kernel 1: partial column sums of exp(x).
// Grid (MM/4/512, ROW_SPLITS) = (2, 128), block 512  → 256 CTAs × 512 thr = 131k threads.
// Each thread owns 4 consecutive columns (float4) and walks 32 rows. Fully coalesced,
// loads within the unrolled loop are independent → high MLP per thread.
__global__ void __launch_bounds__(512) col_partial_exp_sum(const float* __restrict__ xx) {
    const int c4 = blockIdx.x * 512 + threadIdx.x;       // float4 column index
    const int r0 = blockIdx.y * ROWS_PER;
    const float4* __restrict__ x4 = (const float4*)xx;
    const int stride4 = MM / 4;

    float4 acc = make_float4(0.f, 0.f, 0.f, 0.f);
    long base = (long)r0 * stride4 + c4;
#pragma unroll 8
    for (int j = 0; j < ROWS_PER; ++j) {
        float4 v = x4[base + (long)j * stride4];
        acc.x += __expf(v.x);
        acc.y += __expf(v.y);
        acc.z += __expf(v.z);
        acc.w += __expf(v.w);
    }
    ((float4*)g_part)[blockIdx.y * stride4 + c4] = acc;
}

// Kernel 2: fold the 128 partials per column. Grid 16, block 256 (4096 threads).
// Reads are coalesced across threads (stride MM between partial rows).
__global__ void __launch_bounds__(256) reduce_ssum() {
    const int m = blockIdx.x * 256 + threadIdx.x;
    float s = 0.f;
#pragma unroll 16
    for (int k = 0; k < ROW_SPLITS; ++k) s += g_part[k * MM + m];
    g_ssum[m] = s;
}

// Kernel 3: out[i,m] = log( Ssum[m] + expm1(diag[i]) * exp(xx[i,m]) )
//   (== S + log1p(expm1(d_i) * exp(x - S)) exactly, with S = log(Ssum))
// Grid (MM/4/256, NN) = (4, 4096), block 256. Float4 streaming; diag[i] broadcasts
// within the block (one LDG to the same address → L1 broadcast).
__global__ void __launch_bounds__(256) fuse_out(const float* __restrict__ xx,
                                               const float* __restrict__ diag,
                                               float* __restrict__ out) {
    const int i = blockIdx.y;
    const int c4 = blockIdx.x * 256 + threadIdx.x;
    const int stride4 = MM / 4;
    const float em = expm1f(diag[i]);

    const float4* __restrict__ x4 = (const float4*)xx;
    const float4* __restrict__ s4 = (const float4*)g_ssum;

    float4 v = x4[(long)i * stride4 + c4];
    float4 s = s4[c4];

    float4 o;
    o.x = __logf(fmaf(em, __expf(v.x), s.x));
    o.y = __logf(fmaf(em, __expf(v.y), s.y));
    o.z = __logf(fmaf(em, __expf(v.z), s.z));
    o.w = __logf(fmaf(em, __expf(v.w), s.w));

    ((float4*)out)[(long)i * stride4 + c4] = o;
}

extern "C" void kernel_launch(void* const* d_in, const int* in_sizes, int n_in,
                              void* d_out, int out_size) {
    const float* xx   = (const float*)d_in[0];   // (4096, 4096) fp32 row-major
    const float* diag = (const float*)d_in[1];   // (4096,) fp32
    float* out        = (float*)d_out;           // (4096, 4096) fp32

    dim3 g1(MM / 4 / 512, ROW_SPLITS);  // (2, 128)
    col_partial_exp_sum<<<g1, 512>>>(xx);

    reduce_ssum<<<MM / 256, 256>>>();

    dim3 g3(MM / 4 / 256, NN);          // (4, 4096)
    fuse_out<<<g3, 256>>>(xx, diag, out);
}

// round 3
// speedup vs baseline: 1.2353x; 1.1710x over previous
#include <cuda_runtime.h>

// Problem constants (fixed by the reference: xx is (N, M) fp32 row-major, diag is (N,))
#define NN 4096
#define MM 4096
#define ROW_SPLITS 256
#define ROWS_PER (NN / ROW_SPLITS)   // 16 rows per partial block

// Scratch (no allocations allowed) — fully overwritten each launch, replay-safe.
__device__ float g_part[ROW_SPLITS * MM];  // 4 MB: partial exp-sums per (split, column)
__device__ float g_ssum[MM];               // Ssum[m] = sum_j exp(xx[j,m])

// Kernel 1: partial column sums of exp(x).
// Grid (2, 256) = 512 CTAs, block 512  → 262k threads (~85% thread occupancy).
// Each thread owns 4 consecutive columns (float4) and walks 16 rows, fully
// unrolled → 16 independent LDG.128 in flight per thread.
__global__ void __launch_bounds__(512) col_partial_exp_sum(const float* __restrict__ xx) {
    const int c4 = blockIdx.x * 512 + threadIdx.x;       // float4 column index
    const int r0 = blockIdx.y * ROWS_PER;
    const float4* __restrict__ x4 = (const float4*)xx;
    const int stride4 = MM / 4;

    float4 acc = make_float4(0.f, 0.f, 0.f, 0.f);
    long base = (long)r0 * stride4 + c4;
#pragma unroll 16
    for (int j = 0; j < ROWS_PER; ++j) {
        float4 v = x4[base + (long)j * stride4];
        acc.x += __expf(v.x);
        acc.y += __expf(v.y);
        acc.z += __expf(v.z);
        acc.w += __expf(v.w);
    }
    ((float4*)g_part)[blockIdx.y * stride4 + c4] = acc;
}

// Kernel 2: fold the 256 partials per column.
// Grid 32, block 512 organized as (128 columns) x (4 row-chunks); each thread
// sums 64 partials for its column, then a tiny smem fold combines the 4 chunks.
// Loads are coalesced: within a chunk, 128 consecutive threads read 128
// consecutive columns.
__global__ void __launch_bounds__(512) reduce_ssum() {
    __shared__ float sred[4][128];
    const int col   = threadIdx.x & 127;       // 0..127
    const int chunk = threadIdx.x >> 7;        // 0..3
    const int m = blockIdx.x * 128 + col;

    float s = 0.f;
    const int k0 = chunk * (ROW_SPLITS / 4);   // 64 partials per chunk
#pragma unroll 16
    for (int k = 0; k < ROW_SPLITS / 4; ++k)
        s += g_part[(k0 + k) * MM + m];

    sred[chunk][col] = s;
    __syncthreads();
    if (chunk == 0)
        g_ssum[m] = sred[0][col] + sred[1][col] + sred[2][col] + sred[3][col];
}

// Kernel 3: out[i,m] = log( Ssum[m] + expm1(diag[i]) * exp(xx[i,m]) )
//   (== S + log1p(expm1(d_i) * exp(x - S)) exactly, with S = log(Ssum))
// Grid (2, 4096), block 256; each thread handles 2 float4s of row i.
// Output stored with __stcs (streaming / evict-first) so the xx lines that K1
// left in L2 survive for K3's reads.
__global__ void __launch_bounds__(256) fuse_out(const float* __restrict__ xx,
                                               const float* __restrict__ diag,
                                               float* __restrict__ out) {
    const int i = blockIdx.y;
    const int c4 = blockIdx.x * 512 + threadIdx.x;   // first float4 column
    const int stride4 = MM / 4;
    const float em = expm1f(diag[i]);

    const float4* __restrict__ x4 = (const float4*)xx;
    const float4* __restrict__ s4 = (const float4*)g_ssum;
    float4* __restrict__ o4 = (float4*)out;

    const long b = (long)i * stride4;

    float4 v0 = x4[b + c4];
    float4 v1 = x4[b + c4 + 256];
    float4 s0 = s4[c4];
    float4 s1 = s4[c4 + 256];

    float4 o0, o1;
    o0.x = __logf(fmaf(em, __expf(v0.x), s0.x));
    o0.y = __logf(fmaf(em, __expf(v0.y), s0.y));
    o0.z = __logf(fmaf(em, __expf(v0.z), s0.z));
    o0.w = __logf(fmaf(em, __expf(v0.w), s0.w));
    o1.x = __logf(fmaf(em, __expf(v1.x), s1.x));
    o1.y = __logf(fmaf(em, __expf(v1.y), s1.y));
    o1.z = __logf(fmaf(em, __expf(v1.z), s1.z));
    o1.w = __logf(fmaf(em, __expf(v1.w), s1.w));

    __stcs(&o4[b + c4], o0);
    __stcs(&o4[b + c4 + 256], o1);
}

extern "C" void kernel_launch(void* const* d_in, const int* in_sizes, int n_in,
                              void* d_out, int out_size) {
    const float* xx   = (const float*)d_in[0];   // (4096, 4096) fp32 row-major
    const float* diag = (const float*)d_in[1];   // (4096,) fp32
    float* out        = (float*)d_out;           // (4096, 4096) fp32

    dim3 g1(MM / 4 / 512, ROW_SPLITS);  // (2, 256)
    col_partial_exp_sum<<<g1, 512>>>(xx);

    reduce_ssum<<<MM / 128, 512>>>();   // 32 CTAs

    dim3 g3(2, NN);                     // (2, 4096)
    fuse_out<<<g3, 256>>>(xx, diag, out);
}

// round 6
// speedup vs baseline: 1.2596x; 1.0197x over previous
#include <cuda_runtime.h>

// Problem constants (fixed by the reference: xx is (N, M) fp32 row-major, diag is (N,))
#define NN 4096
#define MM 4096
#define ROW_SPLITS 128
#define ROWS_PER (NN / ROW_SPLITS)   // 32 rows per partial block
#define BATCH 8                      // loads staged in registers per inner batch

// Scratch (no allocations allowed) — fully overwritten each launch, replay-safe.
__device__ float g_part[ROW_SPLITS * MM];  // 2 MB: partial exp-sums per (split, column)
__device__ float g_ssum[MM];               // Ssum[m] = sum_j exp(xx[j,m])

// Kernel 1: partial column sums of exp(x).
// Grid (4, 128) = 512 CTAs, block 256. Each thread owns 4 consecutive columns
// (one float4 lane) and walks 32 rows in register-staged batches of 8 — the
// explicit v[8] staging forces ptxas to front-batch 8 independent LDG.128
// (MLP_p1 = 8) instead of interleaving load/exp at 32 regs.
__global__ void __launch_bounds__(256) col_partial_exp_sum(const float* __restrict__ xx) {
    const int c4 = blockIdx.x * 256 + threadIdx.x;       // float4 column index
    const int r0 = blockIdx.y * ROWS_PER;
    const float4* __restrict__ x4 = (const float4*)xx;
    const int stride4 = MM / 4;

    float4 acc = make_float4(0.f, 0.f, 0.f, 0.f);
    long base = (long)r0 * stride4 + c4;

#pragma unroll
    for (int b = 0; b < ROWS_PER / BATCH; ++b) {
        float4 v[BATCH];
#pragma unroll
        for (int j = 0; j < BATCH; ++j)
            v[j] = x4[base + (long)(b * BATCH + j) * stride4];
#pragma unroll
        for (int j = 0; j < BATCH; ++j) {
            acc.x += __expf(v[j].x);
            acc.y += __expf(v[j].y);
            acc.z += __expf(v[j].z);
            acc.w += __expf(v[j].w);
        }
    }
    ((float4*)g_part)[blockIdx.y * stride4 + c4] = acc;
}

// Kernel 2: fold the 128 partials per column.
// Grid 64, block 512 organized as (64 columns) x (8 row-chunks of 16 partials).
// Coalesced: 64 consecutive threads read 64 consecutive columns.
__global__ void __launch_bounds__(512) reduce_ssum() {
    __shared__ float sred[8][64];
    const int col   = threadIdx.x & 63;        // 0..63
    const int chunk = threadIdx.x >> 6;        // 0..7
    const int m = blockIdx.x * 64 + col;

    float s = 0.f;
    const int k0 = chunk * (ROW_SPLITS / 8);   // 16 partials per chunk
#pragma unroll
    for (int k = 0; k < ROW_SPLITS / 8; ++k)
        s += g_part[(k0 + k) * MM + m];

    sred[chunk][col] = s;
    __syncthreads();
    if (chunk == 0) {
        float t = 0.f;
#pragma unroll
        for (int c = 0; c < 8; ++c) t += sred[c][col];
        g_ssum[m] = t;
    }
}

// Kernel 3: out[i,m] = log( Ssum[m] + expm1(diag[i]) * exp(xx[i,m]) )
//   (== S + log1p(expm1(d_i) * exp(x - S)) exactly, with S = log(Ssum))
// Grid 2048 CTAs x 512 thr; each CTA covers exactly 2 rows (2048 float4).
// Per-k row index is CTA-uniform (k-strided chunks of 512 float4 = half a row),
// so the diag load is a warp-uniform broadcast. Loads front-batched so the
// 8-MUFU chain per float4 overlaps the memory stream.
__global__ void __launch_bounds__(512) fuse_out(const float* __restrict__ xx,
                                               const float* __restrict__ diag,
                                               float* __restrict__ out) {
    const int row0 = blockIdx.x * 2;                       // first of the 2 rows
    const int t = threadIdx.x;                             // 0..511
    const long base = (long)blockIdx.x * 2048 + t;

    const float4* __restrict__ x4 = (const float4*)xx;
    const float4* __restrict__ s4 = (const float4*)g_ssum;
    float4* __restrict__ o4 = (float4*)out;

    // k = 0,1 -> row0 (col4 = t, t+512); k = 2,3 -> row0+1
    float4 v[4], s[4];
#pragma unroll
    for (int k = 0; k < 4; ++k) {
        v[k] = x4[base + k * 512];
        s[k] = s4[(k & 1) * 512 + t];
    }
    const float e0 = expm1f(diag[row0]);
    const float e1 = expm1f(diag[row0 + 1]);

#pragma unroll
    for (int k = 0; k < 4; ++k) {
        const float e = (k < 2) ? e0 : e1;
        float4 o;
        o.x = __logf(fmaf(e, __expf(v[k].x), s[k].x));
        o.y = __logf(fmaf(e, __expf(v[k].y), s[k].y));
        o.z = __logf(fmaf(e, __expf(v[k].z), s[k].z));
        o.w = __logf(fmaf(e, __expf(v[k].w), s[k].w));
        o4[base + k * 512] = o;
    }
}

extern "C" void kernel_launch(void* const* d_in, const int* in_sizes, int n_in,
                              void* d_out, int out_size) {
    const float* xx   = (const float*)d_in[0];   // (4096, 4096) fp32 row-major
    const float* diag = (const float*)d_in[1];   // (4096,) fp32
    float* out        = (float*)d_out;           // (4096, 4096) fp32

    dim3 g1(MM / 4 / 256, ROW_SPLITS);  // (4, 128) = 512 CTAs
    col_partial_exp_sum<<<g1, 256>>>(xx);

    reduce_ssum<<<MM / 64, 512>>>();    // 64 CTAs

    fuse_out<<<2048, 512>>>(xx, diag, out);  // 2048 CTAs, 2 rows each
}